// round 15
// baseline (speedup 1.0000x reference)
#include <cuda_runtime.h>

#define TT 2048
#define BB 32
#define HH 256
#define G3 768
#define NS 1024
#define EMBD 63

// ---------- persistent device scratch (no allocations) ----------
__device__ float d_Eg[2][NS][G3];          // bi + embed @ Wi[1:]
__device__ float d_H[2][TT + 1][BB][HH];   // hidden history; sentinel-filled each launch

// ---------- f32x2 helpers ----------
__device__ __forceinline__ unsigned long long pk2(float a, float b) {
    unsigned long long r;
    asm("mov.b64 %0, {%1, %2};" : "=l"(r) : "f"(a), "f"(b));
    return r;
}
__device__ __forceinline__ void fma2(unsigned long long& d, unsigned long long a,
                                     unsigned long long b) {
    asm("fma.rn.f32x2 %0, %1, %2, %0;" : "+l"(d) : "l"(a), "l"(b));
}
__device__ __forceinline__ float2 up2(unsigned long long v) {
    float lo, hi;
    asm("mov.b64 {%0, %1}, %2;" : "=f"(lo), "=f"(hi) : "l"(v));
    return make_float2(lo, hi);
}
// spin one word until it is no longer the sentinel 2.0f
__device__ __forceinline__ float spin_word(const float* p) {
    float x;
    do {
        asm volatile("ld.relaxed.gpu.global.f32 %0, [%1];" : "=f"(x) : "l"(p));
    } while (x == 2.f);
    return x;
}

// =====================================================================
// Kernel 0: fill d_H with the impossible sentinel 2.0f (|h| < 1 always).
// =====================================================================
__global__ void __launch_bounds__(256) hinit_kernel() {
    const size_t total = (size_t)2 * (TT + 1) * BB * HH / 4;
    float4* p = reinterpret_cast<float4*>(&d_H[0][0][0][0]);
    const float4 s = make_float4(2.f, 2.f, 2.f, 2.f);
    for (size_t i = (size_t)blockIdx.x * 256 + threadIdx.x; i < total;
         i += (size_t)gridDim.x * 256)
        p[i] = s;
}

// =====================================================================
// Kernel A: E[dir] = bi + embed @ Wi[1:, :]
// =====================================================================
__global__ void __launch_bounds__(256) precompute_kernel(
    const float* __restrict__ embed,
    const float* __restrict__ Wif, const float* __restrict__ bif,
    const float* __restrict__ Wib, const float* __restrict__ bib)
{
    const int tid = threadIdx.x;
    __shared__ float emb[8][EMBD];
    const int sb = blockIdx.x * 8;
    for (int i = tid; i < 8 * EMBD; i += 256)
        emb[i / EMBD][i % EMBD] = embed[sb * EMBD + i];
    __syncthreads();

    const int c = tid;
    float af0[8], af1[8], af2[8], ab0[8], ab1[8], ab2[8];
#pragma unroll
    for (int s = 0; s < 8; s++) { af0[s]=af1[s]=af2[s]=ab0[s]=ab1[s]=ab2[s]=0.f; }

    for (int e = 0; e < EMBD; e++) {
        const float wf0 = Wif[(1 + e) * G3 + c];
        const float wf1 = Wif[(1 + e) * G3 + 256 + c];
        const float wf2 = Wif[(1 + e) * G3 + 512 + c];
        const float wb0 = Wib[(1 + e) * G3 + c];
        const float wb1 = Wib[(1 + e) * G3 + 256 + c];
        const float wb2 = Wib[(1 + e) * G3 + 512 + c];
#pragma unroll
        for (int s = 0; s < 8; s++) {
            const float x = emb[s][e];
            af0[s] = fmaf(wf0, x, af0[s]);
            af1[s] = fmaf(wf1, x, af1[s]);
            af2[s] = fmaf(wf2, x, af2[s]);
            ab0[s] = fmaf(wb0, x, ab0[s]);
            ab1[s] = fmaf(wb1, x, ab1[s]);
            ab2[s] = fmaf(wb2, x, ab2[s]);
        }
    }
    const float bf0 = bif[c], bf1 = bif[256 + c], bf2 = bif[512 + c];
    const float bb0 = bib[c], bb1 = bib[256 + c], bb2 = bib[512 + c];
#pragma unroll
    for (int s = 0; s < 8; s++) {
        d_Eg[0][sb + s][c]       = af0[s] + bf0;
        d_Eg[0][sb + s][256 + c] = af1[s] + bf1;
        d_Eg[0][sb + s][512 + c] = af2[s] + bf2;
        d_Eg[1][sb + s][c]       = ab0[s] + bb0;
        d_Eg[1][sb + s][256 + c] = ab1[s] + bb1;
        d_Eg[1][sb + s][512 + c] = ab2[s] + bb2;
    }
}

// =====================================================================
// Kernel B: persistent bidirectional GRU scan — sentinel data-polling
// (R12 winner) with SEQUENTIAL-WORD polls: spin word0, verify 1-3.
// Steady-state poll traffic /4 -> no LSU queue jam, faster detect.
// grid 128 = 2 dirs x 8 batch-groups(4 batches) x 8 hidden-slices(32 units)
// block 384 (GEMM: c = tid%96, ks = tid/96, k in [ks*64,+64)).
// =====================================================================
__global__ void __launch_bounds__(384, 1) gru_scan_kernel(
    const float* __restrict__ dur, const int* __restrict__ sid,
    const float* __restrict__ Whf, const float* __restrict__ Whb,
    const float* __restrict__ bhnf, const float* __restrict__ bhnb,
    const float* __restrict__ Wif, const float* __restrict__ Wib)
{
    __shared__ __align__(16) float hsm[2][1024];   // double-buffered h (4b x 256u)
    __shared__ float psum[16 * 96];

    const int tid = threadIdx.x;
    const int dir = blockIdx.x >> 6;
    const int bg  = (blockIdx.x >> 3) & 7;
    const int hs  = blockIdx.x & 7;
    const int u0  = hs * 32;

    const float* Wh  = dir ? Whb : Whf;
    const float* bhn = dir ? bhnb : bhnf;
    const float* Wi  = dir ? Wib : Wif;
    const float* Egd = &d_Eg[dir][0][0];
    float* H = &d_H[dir][0][0][0];

    for (int i = tid; i < 1024; i += 384) hsm[0][i] = 0.f;   // h[0] = 0

    // my 96-column Wh slice in registers (R12 layout, proven)
    const int c  = tid % 96;
    const int ks = tid / 96;                       // k range [ks*64, ks*64+64)
    const int gcol = (c / 32) * 256 + u0 + (c % 32);
    unsigned long long wp[32];
#pragma unroll
    for (int i = 0; i < 32; i++)
        wp[i] = pk2(Wh[(ks * 64 + 2 * i) * G3 + gcol],
                    Wh[(ks * 64 + 2 * i + 1) * G3 + gcol]);

    // gate-thread state (tid < 128: b = tid>>5, u = tid&31)
    const int b = tid >> 5;
    const int u = tid & 31;
    const int gb = bg * 4 + b;
    float wi0r = 0.f, wi0z = 0.f, wi0n = 0.f, bhn_u = 0.f;
    float hprev = 0.f;
    int   sid_cur = 0;
    float dur_cur = 0.f;
    if (tid < 128) {
        wi0r  = Wi[u0 + u];
        wi0z  = Wi[256 + u0 + u];
        wi0n  = Wi[512 + u0 + u];
        bhn_u = bhn[u0 + u];
        const int st = dir ? (TT - 1) : 0;
        sid_cur = sid[gb * TT + st];
        dur_cur = dur[gb * TT + st];
    }
    __syncthreads();

    for (int t = 0; t < TT; ++t) {
        // gate-input gathers (independent of recurrence) — overlap with GEMM
        float er = 0.f, ez = 0.f, en = 0.f;
        int sid_nx = 0; float dur_nx = 0.f;
        if (tid < 128) {
            const float* Er = Egd + (size_t)sid_cur * G3;
            er = __ldg(Er + u0 + u);
            ez = __ldg(Er + 256 + u0 + u);
            en = __ldg(Er + 512 + u0 + u);
            if (t + 1 < TT) {
                const int st = dir ? (TT - 2 - t) : (t + 1);
                sid_nx = sid[gb * TT + st];
                dur_nx = dur[gb * TT + st];
            }
        }

        // GEMM partial over my 64-k slice, reading h[t] from local smem
        const float* hbase = &hsm[t & 1][0] + ks * 64;
        unsigned long long acc[4];
#pragma unroll
        for (int i = 0; i < 4; i++) acc[i] = pk2(0.f, 0.f);
#pragma unroll
        for (int kk = 0; kk < 64; kk += 4) {
            const unsigned long long w0 = wp[kk >> 1];
            const unsigned long long w1 = wp[(kk >> 1) + 1];
#pragma unroll
            for (int bb2 = 0; bb2 < 4; ++bb2) {
                const ulonglong2 hv =
                    *reinterpret_cast<const ulonglong2*>(hbase + bb2 * 256 + kk);
                fma2(acc[bb2], w0, hv.x);
                fma2(acc[bb2], w1, hv.y);
            }
        }
#pragma unroll
        for (int bb2 = 0; bb2 < 4; ++bb2) {
            const float2 a = up2(acc[bb2]);
            psum[(ks * 4 + bb2) * 96 + c] = a.x + a.y;
        }
        __syncthreads();   // bar1: psum ready; hsm[(t+1)&1] free

        if (tid < 128) {
            // gates: reduce 4 k-splits, update state, publish h (relaxed.gpu)
            float hr = 0.f, hz = 0.f, hn = 0.f;
#pragma unroll
            for (int k2 = 0; k2 < 4; k2++) {
                const int base = (k2 * 4 + b) * 96;
                hr += psum[base + u];
                hz += psum[base + 32 + u];
                hn += psum[base + 64 + u];
            }
            const float ir  = fmaf(dur_cur, wi0r, er);
            const float iz  = fmaf(dur_cur, wi0z, ez);
            const float inn = fmaf(dur_cur, wi0n, en);
            const float r = 1.f / (1.f + __expf(-(ir + hr)));
            const float z = 1.f / (1.f + __expf(-(iz + hz)));
            const float n = tanhf(fmaf(r, hn + bhn_u, inn));
            const float hnew = (1.f - z) * n + z * hprev;
            asm volatile("st.relaxed.gpu.global.f32 [%0], %1;"
                         :: "l"(H + ((size_t)(t + 1) * BB + gb) * HH + u0 + u),
                            "f"(hnew) : "memory");
            hprev = hnew;
            sid_cur = sid_nx;
            dur_cur = dur_nx;
        } else if (t + 1 < TT) {
            // stagers: spin on word0 of my span; then verify words 1-3
            // (written by the same warp-wide store -> land together; each
            //  word still individually checked before use = strictly safe)
            const int f = tid - 128;               // 0..255
            const float* src = H + ((size_t)(t + 1) * BB + bg * 4) * HH + f * 4;
            float4 v;
            v.x = spin_word(src + 0);
            v.y = spin_word(src + 1);
            v.z = spin_word(src + 2);
            v.w = spin_word(src + 3);
            reinterpret_cast<float4*>(&hsm[(t + 1) & 1][0])[f] = v;
        }
        __syncthreads();   // bar2: hsm[(t+1)&1] = h[t+1]
    }
}

// =====================================================================
// Kernel C: out[b,t] = fwd[t+1,b,:].Wd[0:256] + bwd[T-t,b,:].Wd[256:512] + bd
// =====================================================================
__global__ void __launch_bounds__(256) out_proj_kernel(
    const float* __restrict__ Wd, const float* __restrict__ bd,
    float* __restrict__ out)
{
    __shared__ float wd[512];
    const int tid = threadIdx.x;
    wd[tid] = Wd[tid];
    wd[tid + 256] = Wd[tid + 256];
    __syncthreads();

    const int warp = tid >> 5, lane = tid & 31;
    const int g = blockIdx.x * 8 + warp;
    const int b = g >> 11;
    const int t = g & 2047;

    const float* hf = &d_H[0][t + 1][b][0];
    const float* hb = &d_H[1][TT - t][b][0];
    float s = 0.f;
#pragma unroll
    for (int i = lane; i < HH; i += 32)
        s = fmaf(hf[i], wd[i], fmaf(hb[i], wd[256 + i], s));
#pragma unroll
    for (int o = 16; o > 0; o >>= 1) s += __shfl_xor_sync(0xffffffffu, s, o);
    if (lane == 0) out[b * TT + t] = s + bd[0];
}

__global__ void nop_kernel() {}

// =====================================================================
extern "C" void kernel_launch(void* const* d_in, const int* in_sizes, int n_in,
                              void* d_out, int out_size)
{
    const float* dur   = (const float*)d_in[0];
    const int*   sid   = (const int*)  d_in[1];
    const float* embed = (const float*)d_in[2];
    const float* Wif   = (const float*)d_in[3];
    const float* Whf   = (const float*)d_in[4];
    const float* bif   = (const float*)d_in[5];
    const float* bhnf  = (const float*)d_in[6];
    const float* Wib   = (const float*)d_in[7];
    const float* Whb   = (const float*)d_in[8];
    const float* bib   = (const float*)d_in[9];
    const float* bhnb  = (const float*)d_in[10];
    const float* Wd    = (const float*)d_in[11];
    const float* bd    = (const float*)d_in[12];
    float* out = (float*)d_out;

    // scan kernel kept as the 4th launch — that's the one ncu captures
    hinit_kernel<<<2048, 256>>>();
    precompute_kernel<<<128, 256>>>(embed, Wif, bif, Wib, bib);
    nop_kernel<<<1, 32>>>();
    gru_scan_kernel<<<128, 384>>>(dur, sid, Whf, Whb, bhnf, bhnb, Wif, Wib);
    out_proj_kernel<<<8192, 256>>>(Wd, bd, out);
}

// round 16
// speedup vs baseline: 1.3164x; 1.3164x over previous
#include <cuda_runtime.h>

#define TT 2048
#define BB 32
#define HH 256
#define G3 768
#define NS 1024
#define EMBD 63

// ---------- persistent device scratch (no allocations) ----------
__device__ float d_Eg[2][NS][G3];          // bi + embed @ Wi[1:]
__device__ float d_H[2][TT + 1][BB][HH];   // hidden history; sentinel-filled each launch

// ---------- f32x2 helpers ----------
__device__ __forceinline__ unsigned long long pk2(float a, float b) {
    unsigned long long r;
    asm("mov.b64 %0, {%1, %2};" : "=l"(r) : "f"(a), "f"(b));
    return r;
}
__device__ __forceinline__ void fma2(unsigned long long& d, unsigned long long a,
                                     unsigned long long b) {
    asm("fma.rn.f32x2 %0, %1, %2, %0;" : "+l"(d) : "l"(a), "l"(b));
}
__device__ __forceinline__ float2 up2(unsigned long long v) {
    float lo, hi;
    asm("mov.b64 {%0, %1}, %2;" : "=f"(lo), "=f"(hi) : "l"(v));
    return make_float2(lo, hi);
}

// =====================================================================
// Kernel 0: fill d_H with the impossible sentinel 2.0f (|h| < 1 always).
// =====================================================================
__global__ void __launch_bounds__(256) hinit_kernel() {
    const size_t total = (size_t)2 * (TT + 1) * BB * HH / 4;
    float4* p = reinterpret_cast<float4*>(&d_H[0][0][0][0]);
    const float4 s = make_float4(2.f, 2.f, 2.f, 2.f);
    for (size_t i = (size_t)blockIdx.x * 256 + threadIdx.x; i < total;
         i += (size_t)gridDim.x * 256)
        p[i] = s;
}

// =====================================================================
// Kernel A: E[dir] = bi + embed @ Wi[1:, :]
// =====================================================================
__global__ void __launch_bounds__(256) precompute_kernel(
    const float* __restrict__ embed,
    const float* __restrict__ Wif, const float* __restrict__ bif,
    const float* __restrict__ Wib, const float* __restrict__ bib)
{
    const int tid = threadIdx.x;
    __shared__ float emb[8][EMBD];
    const int sb = blockIdx.x * 8;
    for (int i = tid; i < 8 * EMBD; i += 256)
        emb[i / EMBD][i % EMBD] = embed[sb * EMBD + i];
    __syncthreads();

    const int c = tid;
    float af0[8], af1[8], af2[8], ab0[8], ab1[8], ab2[8];
#pragma unroll
    for (int s = 0; s < 8; s++) { af0[s]=af1[s]=af2[s]=ab0[s]=ab1[s]=ab2[s]=0.f; }

    for (int e = 0; e < EMBD; e++) {
        const float wf0 = Wif[(1 + e) * G3 + c];
        const float wf1 = Wif[(1 + e) * G3 + 256 + c];
        const float wf2 = Wif[(1 + e) * G3 + 512 + c];
        const float wb0 = Wib[(1 + e) * G3 + c];
        const float wb1 = Wib[(1 + e) * G3 + 256 + c];
        const float wb2 = Wib[(1 + e) * G3 + 512 + c];
#pragma unroll
        for (int s = 0; s < 8; s++) {
            const float x = emb[s][e];
            af0[s] = fmaf(wf0, x, af0[s]);
            af1[s] = fmaf(wf1, x, af1[s]);
            af2[s] = fmaf(wf2, x, af2[s]);
            ab0[s] = fmaf(wb0, x, ab0[s]);
            ab1[s] = fmaf(wb1, x, ab1[s]);
            ab2[s] = fmaf(wb2, x, ab2[s]);
        }
    }
    const float bf0 = bif[c], bf1 = bif[256 + c], bf2 = bif[512 + c];
    const float bb0 = bib[c], bb1 = bib[256 + c], bb2 = bib[512 + c];
#pragma unroll
    for (int s = 0; s < 8; s++) {
        d_Eg[0][sb + s][c]       = af0[s] + bf0;
        d_Eg[0][sb + s][256 + c] = af1[s] + bf1;
        d_Eg[0][sb + s][512 + c] = af2[s] + bf2;
        d_Eg[1][sb + s][c]       = ab0[s] + bb0;
        d_Eg[1][sb + s][256 + c] = ab1[s] + bb1;
        d_Eg[1][sb + s][512 + c] = ab2[s] + bb2;
    }
}

// =====================================================================
// Kernel B: persistent bidirectional GRU scan — TWO interleaved chains
// per CTA with sentinel data-polling (R12 primitives verbatim).
// grid 128 = 2 dirs x 8 q-groups x 8 slices(32 units).
// CTA runs chainA = bg 2q (batches 4q,4q+1), chainB = bg 2q+1
// (batches 4q+2,4q+3); same dir -> shared Wh registers.
// block 384: GEMM c = tid%96, ks = tid/96 (64 k each), 2 batches/chain.
// Phases: GEMM_A | gates_A || stage_B | GEMM_B | gates_B || stage_A.
// Every poll targets data published one GEMM phase earlier -> no spin.
// =====================================================================
__global__ void __launch_bounds__(384, 1) gru_scan_kernel(
    const float* __restrict__ dur, const int* __restrict__ sid,
    const float* __restrict__ Whf, const float* __restrict__ Whb,
    const float* __restrict__ bhnf, const float* __restrict__ bhnb,
    const float* __restrict__ Wif, const float* __restrict__ Wib)
{
    __shared__ __align__(16) float hsmA[2][512];   // chain A h (2 batches x 256)
    __shared__ __align__(16) float hsmB[2][512];   // chain B h
    __shared__ float psum[8 * 96];

    const int tid = threadIdx.x;
    const int dir = blockIdx.x >> 6;
    const int q   = (blockIdx.x >> 3) & 7;
    const int hs  = blockIdx.x & 7;
    const int u0  = hs * 32;

    const float* Wh  = dir ? Whb : Whf;
    const float* bhn = dir ? bhnb : bhnf;
    const float* Wi  = dir ? Wib : Wif;
    const float* Egd = &d_Eg[dir][0][0];
    float* H = &d_H[dir][0][0][0];

    for (int i = tid; i < 512; i += 384) { hsmA[0][i] = 0.f; hsmB[0][i] = 0.f; }

    // my 96-column Wh slice in registers (shared by both chains)
    const int c  = tid % 96;
    const int ks = tid / 96;                       // k range [ks*64, ks*64+64)
    const int gcol = (c / 32) * 256 + u0 + (c % 32);
    unsigned long long wp[32];
#pragma unroll
    for (int i = 0; i < 32; i++)
        wp[i] = pk2(Wh[(ks * 64 + 2 * i) * G3 + gcol],
                    Wh[(ks * 64 + 2 * i + 1) * G3 + gcol]);

    // gate-thread state (tid < 64: b = tid>>5 in {0,1}, u = tid&31)
    const int b = tid >> 5;
    const int u = tid & 31;
    const int gbA = q * 4 + b;
    const int gbB = q * 4 + 2 + b;
    float wi0r = 0.f, wi0z = 0.f, wi0n = 0.f, bhn_u = 0.f;
    float hprevA = 0.f, hprevB = 0.f;
    int   sidA = 0, sidB = 0;
    float durA = 0.f, durB = 0.f;
    if (tid < 64) {
        wi0r  = Wi[u0 + u];
        wi0z  = Wi[256 + u0 + u];
        wi0n  = Wi[512 + u0 + u];
        bhn_u = bhn[u0 + u];
        const int st = dir ? (TT - 1) : 0;
        sidA = sid[gbA * TT + st]; durA = dur[gbA * TT + st];
        sidB = sid[gbB * TT + st]; durB = dur[gbB * TT + st];
    }
    const int f = tid - 256;                       // stager id 0..127 (tid>=256)
    __syncthreads();

    for (int t = 0; t < TT; ++t) {
        // prefetch gate inputs for both chains (consumed in P2/P4)
        float erA=0.f, ezA=0.f, enA=0.f, erB=0.f, ezB=0.f, enB=0.f;
        int sidAn = 0, sidBn = 0; float durAn = 0.f, durBn = 0.f;
        if (tid < 64) {
            const float* EA = Egd + (size_t)sidA * G3;
            const float* EB = Egd + (size_t)sidB * G3;
            erA = __ldg(EA + u0 + u); ezA = __ldg(EA + 256 + u0 + u); enA = __ldg(EA + 512 + u0 + u);
            erB = __ldg(EB + u0 + u); ezB = __ldg(EB + 256 + u0 + u); enB = __ldg(EB + 512 + u0 + u);
            if (t + 1 < TT) {
                const int st = dir ? (TT - 2 - t) : (t + 1);
                sidAn = sid[gbA * TT + st]; durAn = dur[gbA * TT + st];
                sidBn = sid[gbB * TT + st]; durBn = dur[gbB * TT + st];
            }
        }

        // ---- P1: GEMM_A over hsmA[t&1] ----
        {
            const float* hbase = &hsmA[t & 1][0] + ks * 64;
            unsigned long long acc0 = pk2(0.f, 0.f), acc1 = pk2(0.f, 0.f);
#pragma unroll
            for (int kk = 0; kk < 64; kk += 4) {
                const unsigned long long w0 = wp[kk >> 1];
                const unsigned long long w1 = wp[(kk >> 1) + 1];
                const ulonglong2 h0 = *reinterpret_cast<const ulonglong2*>(hbase + kk);
                const ulonglong2 h1 = *reinterpret_cast<const ulonglong2*>(hbase + 256 + kk);
                fma2(acc0, w0, h0.x); fma2(acc0, w1, h0.y);
                fma2(acc1, w0, h1.x); fma2(acc1, w1, h1.y);
            }
            const float2 a0 = up2(acc0), a1 = up2(acc1);
            psum[(ks * 2 + 0) * 96 + c] = a0.x + a0.y;
            psum[(ks * 2 + 1) * 96 + c] = a1.x + a1.y;
        }
        __syncthreads();   // bar1

        // ---- P2: gates_A  ||  stagers fetch h_B(t) (published last iter P4) ----
        if (tid < 64) {
            float hr = 0.f, hz = 0.f, hn = 0.f;
#pragma unroll
            for (int k2 = 0; k2 < 4; k2++) {
                const int base = (k2 * 2 + b) * 96;
                hr += psum[base + u];
                hz += psum[base + 32 + u];
                hn += psum[base + 64 + u];
            }
            const float ir  = fmaf(durA, wi0r, erA);
            const float iz  = fmaf(durA, wi0z, ezA);
            const float inn = fmaf(durA, wi0n, enA);
            const float r = 1.f / (1.f + __expf(-(ir + hr)));
            const float z = 1.f / (1.f + __expf(-(iz + hz)));
            const float n = tanhf(fmaf(r, hn + bhn_u, inn));
            const float hnew = (1.f - z) * n + z * hprevA;
            asm volatile("st.relaxed.gpu.global.f32 [%0], %1;"
                         :: "l"(H + ((size_t)(t + 1) * BB + gbA) * HH + u0 + u),
                            "f"(hnew) : "memory");
            hprevA = hnew; sidA = sidAn; durA = durAn;
        } else if (f >= 0 && t > 0) {
            const float* src = H + ((size_t)t * BB + q * 4 + 2) * HH + f * 4;
            float x0, x1, x2, x3;
            do {
                asm volatile("ld.relaxed.gpu.global.f32 %0, [%1];" : "=f"(x0) : "l"(src + 0));
                asm volatile("ld.relaxed.gpu.global.f32 %0, [%1];" : "=f"(x1) : "l"(src + 1));
                asm volatile("ld.relaxed.gpu.global.f32 %0, [%1];" : "=f"(x2) : "l"(src + 2));
                asm volatile("ld.relaxed.gpu.global.f32 %0, [%1];" : "=f"(x3) : "l"(src + 3));
            } while (x0 == 2.f || x1 == 2.f || x2 == 2.f || x3 == 2.f);
            float4 v; v.x = x0; v.y = x1; v.z = x2; v.w = x3;
            reinterpret_cast<float4*>(&hsmB[t & 1][0])[f] = v;
        }
        __syncthreads();   // bar2

        // ---- P3: GEMM_B over hsmB[t&1] ----
        {
            const float* hbase = &hsmB[t & 1][0] + ks * 64;
            unsigned long long acc0 = pk2(0.f, 0.f), acc1 = pk2(0.f, 0.f);
#pragma unroll
            for (int kk = 0; kk < 64; kk += 4) {
                const unsigned long long w0 = wp[kk >> 1];
                const unsigned long long w1 = wp[(kk >> 1) + 1];
                const ulonglong2 h0 = *reinterpret_cast<const ulonglong2*>(hbase + kk);
                const ulonglong2 h1 = *reinterpret_cast<const ulonglong2*>(hbase + 256 + kk);
                fma2(acc0, w0, h0.x); fma2(acc0, w1, h0.y);
                fma2(acc1, w0, h1.x); fma2(acc1, w1, h1.y);
            }
            const float2 a0 = up2(acc0), a1 = up2(acc1);
            psum[(ks * 2 + 0) * 96 + c] = a0.x + a0.y;
            psum[(ks * 2 + 1) * 96 + c] = a1.x + a1.y;
        }
        __syncthreads();   // bar3

        // ---- P4: gates_B  ||  stagers fetch h_A(t+1) (published in P2) ----
        if (tid < 64) {
            float hr = 0.f, hz = 0.f, hn = 0.f;
#pragma unroll
            for (int k2 = 0; k2 < 4; k2++) {
                const int base = (k2 * 2 + b) * 96;
                hr += psum[base + u];
                hz += psum[base + 32 + u];
                hn += psum[base + 64 + u];
            }
            const float ir  = fmaf(durB, wi0r, erB);
            const float iz  = fmaf(durB, wi0z, ezB);
            const float inn = fmaf(durB, wi0n, enB);
            const float r = 1.f / (1.f + __expf(-(ir + hr)));
            const float z = 1.f / (1.f + __expf(-(iz + hz)));
            const float n = tanhf(fmaf(r, hn + bhn_u, inn));
            const float hnew = (1.f - z) * n + z * hprevB;
            asm volatile("st.relaxed.gpu.global.f32 [%0], %1;"
                         :: "l"(H + ((size_t)(t + 1) * BB + gbB) * HH + u0 + u),
                            "f"(hnew) : "memory");
            hprevB = hnew; sidB = sidBn; durB = durBn;
        } else if (f >= 0) {
            const float* src = H + ((size_t)(t + 1) * BB + q * 4) * HH + f * 4;
            float x0, x1, x2, x3;
            do {
                asm volatile("ld.relaxed.gpu.global.f32 %0, [%1];" : "=f"(x0) : "l"(src + 0));
                asm volatile("ld.relaxed.gpu.global.f32 %0, [%1];" : "=f"(x1) : "l"(src + 1));
                asm volatile("ld.relaxed.gpu.global.f32 %0, [%1];" : "=f"(x2) : "l"(src + 2));
                asm volatile("ld.relaxed.gpu.global.f32 %0, [%1];" : "=f"(x3) : "l"(src + 3));
            } while (x0 == 2.f || x1 == 2.f || x2 == 2.f || x3 == 2.f);
            float4 v; v.x = x0; v.y = x1; v.z = x2; v.w = x3;
            reinterpret_cast<float4*>(&hsmA[(t + 1) & 1][0])[f] = v;
        }
        __syncthreads();   // bar4
    }
}

// =====================================================================
// Kernel C: out[b,t] = fwd[t+1,b,:].Wd[0:256] + bwd[T-t,b,:].Wd[256:512] + bd
// =====================================================================
__global__ void __launch_bounds__(256) out_proj_kernel(
    const float* __restrict__ Wd, const float* __restrict__ bd,
    float* __restrict__ out)
{
    __shared__ float wd[512];
    const int tid = threadIdx.x;
    wd[tid] = Wd[tid];
    wd[tid + 256] = Wd[tid + 256];
    __syncthreads();

    const int warp = tid >> 5, lane = tid & 31;
    const int g = blockIdx.x * 8 + warp;
    const int b = g >> 11;
    const int t = g & 2047;

    const float* hf = &d_H[0][t + 1][b][0];
    const float* hb = &d_H[1][TT - t][b][0];
    float s = 0.f;
#pragma unroll
    for (int i = lane; i < HH; i += 32)
        s = fmaf(hf[i], wd[i], fmaf(hb[i], wd[256 + i], s));
#pragma unroll
    for (int o = 16; o > 0; o >>= 1) s += __shfl_xor_sync(0xffffffffu, s, o);
    if (lane == 0) out[b * TT + t] = s + bd[0];
}

__global__ void nop_kernel() {}

// =====================================================================
extern "C" void kernel_launch(void* const* d_in, const int* in_sizes, int n_in,
                              void* d_out, int out_size)
{
    const float* dur   = (const float*)d_in[0];
    const int*   sid   = (const int*)  d_in[1];
    const float* embed = (const float*)d_in[2];
    const float* Wif   = (const float*)d_in[3];
    const float* Whf   = (const float*)d_in[4];
    const float* bif   = (const float*)d_in[5];
    const float* bhnf  = (const float*)d_in[6];
    const float* Wib   = (const float*)d_in[7];
    const float* Whb   = (const float*)d_in[8];
    const float* bib   = (const float*)d_in[9];
    const float* bhnb  = (const float*)d_in[10];
    const float* Wd    = (const float*)d_in[11];
    const float* bd    = (const float*)d_in[12];
    float* out = (float*)d_out;

    // scan kernel kept as the 4th launch — that's the one ncu captures
    hinit_kernel<<<2048, 256>>>();
    precompute_kernel<<<128, 256>>>(embed, Wif, bif, Wib, bib);
    nop_kernel<<<1, 32>>>();
    gru_scan_kernel<<<128, 384>>>(dur, sid, Whf, Whb, bhnf, bhnb, Wif, Wib);
    out_proj_kernel<<<8192, 256>>>(Wd, bd, out);
}